// round 15
// baseline (speedup 1.0000x reference)
#include <cuda_runtime.h>

// ---------------------------------------------------------------------------
// ModelBasedNet: MLP -> softmax risk budgets -> per-sample risk-budget QP via
// damped Newton, Woodbury on the exact rank-64 structure of Sigma.
// Round 15: round-9 base (best passing: 641.7us, rel_err 1.0e-6) with exactly
// one change: pipelined double-buffered triangular sweeps (16 -> 8 barriers,
// apply-phase overlapped with next block's diagonal solve). Math identical.
// Outputs: z (512x200) then b (512x200) into d_out.
// ---------------------------------------------------------------------------

constexpr int BATCH = 512;
constexpr int NFE   = 128;
constexpr int NAS   = 200;
constexpr int HID   = 256;
constexpr int NR    = 64;    // rank of Sigma - 0.1I
constexpr int NIT   = 20;
constexpr int LST   = 68;    // U row stride (17 quads -> conflict-free)
constexpr int MST   = 65;    // Mm row stride
constexpr int NTILE = 136;   // lower-triangle 4x4 tiles of 64x64
constexpr int GRID2 = 304;
constexpr float ALPHA_LR = 0.01f;
constexpr float BMIN     = 1e-4f;
constexpr float SIG_DIAG = 0.1f;
constexpr float KKT_TOL  = 1e-3f;

// smem layout (floats)
constexpr int OFF_LM  = 0;                    // 200*68 = 13600 (U)
constexpr int OFF_MM  = OFF_LM + NAS * LST;   // 64*65  = 4160
constexpr int OFF_GP  = OFF_MM + NR * MST;    // 2*136*16 = 4352
constexpr int OFF_YV  = OFF_GP + 2 * NTILE * 16;
constexpr int OFF_BV  = OFF_YV + NAS;
constexpr int OFF_WV  = OFF_BV + NAS;
constexpr int OFF_EV  = OFF_WV + NAS;
constexpr int OFF_DY  = OFF_EV + NAS;
constexpr int OFF_DG  = OFF_DY + NAS;         // pivot diag (200)
constexpr int OFF_TY  = OFF_DG + NAS;         // 64
constexpr int OFF_MS  = OFF_TY + NR;          // 64
constexpr int OFF_UV  = OFF_MS + NR;          // 64
constexpr int OFF_MD  = OFF_UV + NR;          // 64
constexpr int OFF_RED = OFF_MD + NR;          // 512
constexpr int OFF_TB  = OFF_RED + 512;        // 32 (double-buffered)
constexpr int OFF_LB  = OFF_TB + 32;          // 32
constexpr int OFF_RI  = OFF_LB + 32;          // 32 (int)
constexpr int SMEM_FLOATS = OFF_RI + 32;
constexpr int SMEM_BYTES  = SMEM_FLOATS * 4;

__device__ float g_bc[BATCH * NAS];
__device__ unsigned int g_work;

// ---- block reductions (512 threads, 3 barriers) ----------------------------
__device__ __forceinline__ float blk_sum(float v, float* red, int tid) {
    __syncthreads();
    #pragma unroll
    for (int o = 16; o > 0; o >>= 1) v += __shfl_xor_sync(0xffffffffu, v, o);
    if ((tid & 31) == 0) red[tid >> 5] = v;
    __syncthreads();
    if (tid < 16) {
        float x = red[tid];
        #pragma unroll
        for (int o = 8; o > 0; o >>= 1) x += __shfl_xor_sync(0xffffu, x, o);
        if (tid == 0) red[0] = x;
    }
    __syncthreads();
    return red[0];
}
__device__ __forceinline__ float blk_max(float v, float* red, int tid) {
    __syncthreads();
    #pragma unroll
    for (int o = 16; o > 0; o >>= 1) v = fmaxf(v, __shfl_xor_sync(0xffffffffu, v, o));
    if ((tid & 31) == 0) red[tid >> 5] = v;
    __syncthreads();
    if (tid < 16) {
        float x = red[tid];
        #pragma unroll
        for (int o = 8; o > 0; o >>= 1) x = fmaxf(x, __shfl_xor_sync(0xffffu, x, o));
        if (tid == 0) red[0] = x;
    }
    __syncthreads();
    return red[0];
}
__device__ __forceinline__ float blk_min(float v, float* red, int tid) {
    __syncthreads();
    #pragma unroll
    for (int o = 16; o > 0; o >>= 1) v = fminf(v, __shfl_xor_sync(0xffffffffu, v, o));
    if ((tid & 31) == 0) red[tid >> 5] = v;
    __syncthreads();
    if (tid < 16) {
        float x = red[tid];
        #pragma unroll
        for (int o = 8; o > 0; o >>= 1) x = fminf(x, __shfl_xor_sync(0xffffu, x, o));
        if (tid == 0) red[0] = x;
    }
    __syncthreads();
    return red[0];
}

// ---- shuffle-register 8x8 diagonal block factorization (one warp) ----------
__device__ __forceinline__ void diag_factor_rs(
    float* M, int st, float* dinv8, float* Lblk, int k0, int lane)
{
    float row[8];
    float dinv_own = 0.f;
    float* base = M + (size_t)(k0 + lane) * st + k0;   // valid only lane<8
    if (lane < 8) {
        #pragma unroll
        for (int j = 0; j < 8; ++j) row[j] = (j <= lane) ? base[j] : 0.f;
    } else {
        #pragma unroll
        for (int j = 0; j < 8; ++j) row[j] = 0.f;
    }
    #pragma unroll
    for (int k = 0; k < 8; ++k) {
        float dk   = __shfl_sync(0xffffffffu, row[k], k);
        float dinv = 1.0f / dk;
        if (lane == k) dinv_own = dinv;
        float f = row[k] * dinv;
        #pragma unroll
        for (int j = k + 1; j < 8; ++j) {
            float c = __shfl_sync(0xffffffffu, row[k], j);
            if (lane >= j) row[j] -= f * c;
        }
    }
    if (lane < 8) {
        #pragma unroll
        for (int j = 0; j < 8; ++j)
            if (j <= lane) base[j] = row[j];
        dinv8[lane] = dinv_own;
    }
    #pragma unroll
    for (int c = 0; c < 8; ++c) {
        float ic = __shfl_sync(0xffffffffu, dinv_own, c);
        if (lane < 8 && c < lane)
            Lblk[(lane * (lane - 1)) / 2 + c] = row[c] * ic;
    }
}

__device__ __forceinline__ void block_apply8(float* a, const float* Lblk) {
    a[1] -= a[0] * Lblk[0];
    a[2] -= a[0] * Lblk[1] + a[1] * Lblk[2];
    a[3] -= a[0] * Lblk[3] + a[1] * Lblk[4] + a[2] * Lblk[5];
    a[4] -= a[0] * Lblk[6] + a[1] * Lblk[7] + a[2] * Lblk[8] + a[3] * Lblk[9];
    a[5] -= a[0] * Lblk[10] + a[1] * Lblk[11] + a[2] * Lblk[12] + a[3] * Lblk[13]
          + a[4] * Lblk[14];
    a[6] -= a[0] * Lblk[15] + a[1] * Lblk[16] + a[2] * Lblk[17] + a[3] * Lblk[18]
          + a[4] * Lblk[19] + a[5] * Lblk[20];
    a[7] -= a[0] * Lblk[21] + a[1] * Lblk[22] + a[2] * Lblk[23] + a[3] * Lblk[24]
          + a[4] * Lblk[25] + a[5] * Lblk[26] + a[6] * Lblk[27];
}

// ---------------------------------------------------------------------------
__global__ __launch_bounds__(256) void mlp_kernel(
    const float* __restrict__ x,
    const float* __restrict__ W1, const float* __restrict__ b1,
    const float* __restrict__ W2, const float* __restrict__ b2,
    float* __restrict__ out)
{
    __shared__ float xs[NFE];
    __shared__ float hs[HID];
    __shared__ float ls[NAS];
    __shared__ float red[256];

    if (blockIdx.x == 0 && threadIdx.x == 0) g_work = 0;

    const int s    = blockIdx.x;
    const int tid  = threadIdx.x;
    const int warp = tid >> 5;
    const int lane = tid & 31;

    if (tid < NFE) xs[tid] = x[s * NFE + tid];
    __syncthreads();

    for (int r = 0; r < 32; ++r) {
        int j = warp * 32 + r;
        const float4* w = (const float4*)(W1 + (size_t)j * NFE);
        float4 a = w[lane];
        int k = lane * 4;
        float acc = a.x * xs[k] + a.y * xs[k + 1] + a.z * xs[k + 2] + a.w * xs[k + 3];
        #pragma unroll
        for (int o = 16; o > 0; o >>= 1) acc += __shfl_down_sync(0xffffffffu, acc, o);
        if (lane == 0) {
            float v = acc + b1[j];
            hs[j] = (v >= 0.f) ? v : ALPHA_LR * v;
        }
    }
    __syncthreads();

    for (int r = 0; r < 25; ++r) {
        int j = warp * 25 + r;
        const float4* w = (const float4*)(W2 + (size_t)j * HID);
        float acc = 0.f;
        #pragma unroll
        for (int c = 0; c < 2; ++c) {
            float4 a = w[lane * 2 + c];
            int k = (lane * 2 + c) * 4;
            acc += a.x * hs[k] + a.y * hs[k + 1] + a.z * hs[k + 2] + a.w * hs[k + 3];
        }
        #pragma unroll
        for (int o = 16; o > 0; o >>= 1) acc += __shfl_down_sync(0xffffffffu, acc, o);
        if (lane == 0) ls[j] = acc + b2[j];
    }
    __syncthreads();

    red[tid] = (tid < NAS) ? ls[tid] : -3.0e38f;
    __syncthreads();
    for (int o = 128; o > 0; o >>= 1) {
        if (tid < o) red[tid] = fmaxf(red[tid], red[tid + o]);
        __syncthreads();
    }
    float m = red[0];
    __syncthreads();

    float e = (tid < NAS) ? expf(ls[tid] - m) : 0.f;
    red[tid] = e;
    __syncthreads();
    for (int o = 128; o > 0; o >>= 1) {
        if (tid < o) red[tid] += red[tid + o];
        __syncthreads();
    }
    float denom = red[0];
    __syncthreads();

    float bb = e / denom;
    if (tid < NAS) out[(size_t)BATCH * NAS + (size_t)s * NAS + tid] = bb;

    float bcv = fmaxf(bb, BMIN);
    red[tid] = (tid < NAS) ? bcv : 0.f;
    __syncthreads();
    for (int o = 128; o > 0; o >>= 1) {
        if (tid < o) red[tid] += red[tid + o];
        __syncthreads();
    }
    float s2 = red[0];
    __syncthreads();
    if (tid < NAS) g_bc[s * NAS + tid] = bcv / s2;
}

// ---------------------------------------------------------------------------
__global__ __launch_bounds__(512, 2) void newton_kernel(
    const float* __restrict__ Sigma, float* __restrict__ out_z)
{
    extern __shared__ float sm[];
    float* Um    = sm + OFF_LM;
    float* Mm    = sm + OFF_MM;
    float* Gp    = sm + OFF_GP;
    float* yv    = sm + OFF_YV;
    float* bv    = sm + OFF_BV;
    float* wv    = sm + OFF_WV;
    float* ev    = sm + OFF_EV;
    float* dyv   = sm + OFF_DY;
    float* diag  = sm + OFF_DG;
    float* tyv   = sm + OFF_TY;
    float* msol  = sm + OFF_MS;
    float* uv    = sm + OFF_UV;
    float* mdinv = sm + OFF_MD;
    float* red   = sm + OFF_RED;
    float* tb    = sm + OFF_TB;     // 2 x 16 double buffer
    float* Lblk  = sm + OFF_LB;
    int*   redi  = (int*)(sm + OFF_RI);

    __shared__ int s_sample;

    const int tid  = threadIdx.x;
    const int wid  = tid >> 5;
    const int lane = tid & 31;

    // gram tile assignment (fixed per thread)
    const bool gact = (tid < 3 * NTILE);
    int tPt = 0, tQt = 0, tIdx = 0, tI0 = 0, tIe = 0;
    if (gact) {
        tIdx = tid % NTILE;
        int h = tid / NTILE;
        int p = (int)((sqrtf(8.f * (float)tIdx + 1.f) - 1.f) * 0.5f);
        while (p * (p + 1) / 2 > tIdx) --p;
        while ((p + 1) * (p + 2) / 2 <= tIdx) ++p;
        tPt = p;
        tQt = tIdx - p * (p + 1) / 2;
        tI0 = h * 67;
        tIe = (h == 2) ? NAS : tI0 + 67;
    }

    // U^T * vec -> outv[64]
    auto utv = [&](const float* v, float* outv) {
        int c = tid & 63, h = tid >> 6;
        int i0 = h * 25;
        float acc = 0.f;
        #pragma unroll 5
        for (int i = i0; i < i0 + 25; ++i)
            acc = fmaf(Um[i * LST + c], v[i], acc);
        red[tid] = acc;
        __syncthreads();
        if (tid < NR) {
            float t2 = 0.f;
            #pragma unroll
            for (int h2 = 0; h2 < 8; ++h2) t2 += red[tid + 64 * h2];
            outv[tid] = t2;
        }
        __syncthreads();
    };

    // (U * t64)_i for row i
    auto urow_dot = [&](int i, const float* t64) -> float {
        const float4* lr  = (const float4*)(Um + i * LST);
        const float4* tv4 = (const float4*)t64;
        float acc = 0.f;
        #pragma unroll
        for (int c = 0; c < 16; ++c) {
            float4 a = lr[c], b4 = tv4[c];
            acc = fmaf(a.x, b4.x, acc); acc = fmaf(a.y, b4.y, acc);
            acc = fmaf(a.z, b4.z, acc); acc = fmaf(a.w, b4.w, acc);
        }
        return acc;
    };

    for (;;) {
        if (tid == 0) s_sample = (int)atomicAdd(&g_work, 1u);
        __syncthreads();
        const int s = s_sample;
        if (s >= BATCH) break;

        const float* S = Sigma + (size_t)s * NAS * NAS;
        if (tid < NAS) {
            bv[tid]   = g_bc[s * NAS + tid];
            diag[tid] = S[(size_t)tid * NAS + tid] - SIG_DIAG;
        }
        __syncthreads();

        // ======== setup: diagonally-pivoted Cholesky, 64 columns ===========
        for (int k = 0; k < NR; ++k) {
            // warp 0: argmax of residual diagonal
            if (tid < 32) {
                float v = -1e30f; int ix = 0;
                for (int i = lane; i < NAS; i += 32) {
                    float d = diag[i];
                    if (d > v) { v = d; ix = i; }
                }
                #pragma unroll
                for (int o = 16; o > 0; o >>= 1) {
                    float ov = __shfl_xor_sync(0xffffffffu, v, o);
                    int   oi = __shfl_xor_sync(0xffffffffu, ix, o);
                    if (ov > v) { v = ov; ix = oi; }
                }
                if (lane == 0) { red[0] = v; redi[0] = ix; }
            }
            __syncthreads();
            const int   p  = redi[0];
            const float rs = rsqrtf(fmaxf(red[0], 1e-20f));

            // column k: U[:,k] = (Sigma[:,p] - U U[p,:k]^T) * rs
            if (tid < NAS) {
                float acc = S[(size_t)p * NAS + tid];
                if (tid == p) acc -= SIG_DIAG;
                const float4* Ui4 = (const float4*)(Um + tid * LST);
                const float4* Up4 = (const float4*)(Um + p * LST);
                int k4 = k >> 2;
                for (int c = 0; c < k4; ++c) {
                    float4 a = Ui4[c], b4 = Up4[c];
                    acc -= a.x * b4.x; acc -= a.y * b4.y;
                    acc -= a.z * b4.z; acc -= a.w * b4.w;
                }
                for (int c = k4 * 4; c < k; ++c)
                    acc -= Um[tid * LST + c] * Um[p * LST + c];
                float val = acc * rs;
                Um[tid * LST + k] = val;
                if (tid == p) diag[tid] = -1e30f;
                else          diag[tid] -= val * val;
            }
            __syncthreads();
        }

        // ======== y0 = b / sqrt(b'Sb),  b'Sb = |U^T b|^2 + 0.1|b|^2 ========
        utv(bv, tyv);
        {
            float q = 0.f;
            if (tid < NR)  q += tyv[tid] * tyv[tid];
            if (tid < NAS) q += SIG_DIAG * bv[tid] * bv[tid];
            float Q = blk_sum(q, red, tid);
            if (tid < NAS) yv[tid] = bv[tid] * rsqrtf(Q);
            __syncthreads();
        }

        // ======== Newton iterations =========================================
        for (int it = 0; it < NIT; ++it) {
            // Sy = U(U^T y) + 0.1 y ; g = b/y - Sy ; E = 0.1 + b/y^2
            utv(yv, tyv);
            float kkt = 0.f;
            if (tid < NAS) {
                float sy = urow_dot(tid, tyv) + SIG_DIAG * yv[tid];
                float yy = yv[tid];
                float g  = bv[tid] / yy - sy;
                float E  = SIG_DIAG + bv[tid] / (yy * yy);
                float ei = 1.0f / E;
                ev[tid] = ei;
                wv[tid] = ei * g;
                kkt = fabsf(g) * yy / bv[tid];
            }
            const bool last = (blk_max(kkt, red, tid) < KKT_TOL);

            // ---- gram: lower triangle of Mm = U^T E^{-1} U (+I) ----
            if (gact) {
                const float* lp = Um + 4 * tPt;
                const float* lq = Um + 4 * tQt;
                float acc[16];
                #pragma unroll
                for (int e = 0; e < 16; ++e) acc[e] = 0.f;
                for (int i = tI0; i < tIe; ++i) {
                    float4 a  = *(const float4*)(lp + i * LST);
                    float4 b4 = *(const float4*)(lq + i * LST);
                    float e = ev[i];
                    float4 be = make_float4(b4.x * e, b4.y * e, b4.z * e, b4.w * e);
                    acc[0]  = fmaf(a.x, be.x, acc[0]);  acc[1]  = fmaf(a.x, be.y, acc[1]);
                    acc[2]  = fmaf(a.x, be.z, acc[2]);  acc[3]  = fmaf(a.x, be.w, acc[3]);
                    acc[4]  = fmaf(a.y, be.x, acc[4]);  acc[5]  = fmaf(a.y, be.y, acc[5]);
                    acc[6]  = fmaf(a.y, be.z, acc[6]);  acc[7]  = fmaf(a.y, be.w, acc[7]);
                    acc[8]  = fmaf(a.z, be.x, acc[8]);  acc[9]  = fmaf(a.z, be.y, acc[9]);
                    acc[10] = fmaf(a.z, be.z, acc[10]); acc[11] = fmaf(a.z, be.w, acc[11]);
                    acc[12] = fmaf(a.w, be.x, acc[12]); acc[13] = fmaf(a.w, be.y, acc[13]);
                    acc[14] = fmaf(a.w, be.z, acc[14]); acc[15] = fmaf(a.w, be.w, acc[15]);
                }
                if (tid < NTILE) {
                    #pragma unroll
                    for (int e = 0; e < 16; ++e)
                        Mm[(4 * tPt + (e >> 2)) * MST + 4 * tQt + (e & 3)] = acc[e];
                } else {
                    float* gp = Gp + (tid / NTILE - 1) * (NTILE * 16) + tIdx * 16;
                    #pragma unroll
                    for (int e = 0; e < 16; ++e) gp[e] = acc[e];
                }
            }
            __syncthreads();
            for (int idx = tid; idx < NR * NR; idx += 512) {
                int row = idx >> 6, col = idx & 63;
                if (col <= row) {
                    int rp = row >> 2;
                    int ti = rp * (rp + 1) / 2 + (col >> 2);
                    int e  = (row & 3) * 4 + (col & 3);
                    float v = Mm[row * MST + col]
                            + Gp[ti * 16 + e] + Gp[NTILE * 16 + ti * 16 + e];
                    if (row == col) v += 1.0f;
                    Mm[row * MST + col] = v;
                }
            }
            __syncthreads();

            // ---- Cholesky of Mm (64, unscaled LDL, panels of 8) ----
            for (int k0 = 0; k0 < NR; k0 += 8) {
                const int k1 = k0 + 8;
                if (tid < 32) diag_factor_rs(Mm, MST, mdinv + k0, Lblk, k0, lane);
                __syncthreads();
                if (k1 >= NR) break;
                const int m = NR - k1;
                if (tid < m) {
                    float* rp = Mm + (size_t)(k1 + tid) * MST + k0;
                    float a[8];
                    #pragma unroll
                    for (int c = 0; c < 8; ++c) a[c] = rp[c];
                    block_apply8(a, Lblk);
                    #pragma unroll
                    for (int c = 0; c < 8; ++c) rp[c] = a[c];
                }
                __syncthreads();
                for (int i = k1 + wid; i < NR; i += 16) {
                    const float* rp = Mm + (size_t)i * MST + k0;
                    float f[8];
                    #pragma unroll
                    for (int c = 0; c < 8; ++c) f[c] = rp[c] * mdinv[k0 + c];
                    int width = i - k1 + 1;
                    for (int jo = lane; jo < width; jo += 32) {
                        const float* aj = Mm + (size_t)(k1 + jo) * MST + k0;
                        float d0 = f[0] * aj[0], e0 = f[1] * aj[1];
                        d0 = fmaf(f[2], aj[2], d0); e0 = fmaf(f[3], aj[3], e0);
                        d0 = fmaf(f[4], aj[4], d0); e0 = fmaf(f[5], aj[5], e0);
                        d0 = fmaf(f[6], aj[6], d0); e0 = fmaf(f[7], aj[7], e0);
                        Mm[(size_t)i * MST + k1 + jo] -= (d0 + e0);
                    }
                }
                __syncthreads();
            }

            // ---- msol = U^T w ; solve M u = msol (pipelined sweeps) ----
            utv(wv, msol);
            {
                float* tbp = tb;
                float* tbc = tb + 16;
                // forward: tbp holds block b-1's t; warp 0 applies it to its
                // own 16 rows then solves; warps 1+ apply to rows >= k1.
                #pragma unroll 1
                for (int b = 0; b < 4; ++b) {
                    const int k0 = 16 * b;
                    if (wid == 0) {
                        float zi = 0.f, di = 0.f, rowk[16];
                        if (lane < 16) {
                            zi = msol[k0 + lane];
                            di = mdinv[k0 + lane];
                            if (b > 0) {
                                const float* rp = Mm + (size_t)(k0 + lane) * MST + (k0 - 16);
                                float acc = 0.f;
                                #pragma unroll
                                for (int c = 0; c < 16; ++c) acc = fmaf(rp[c], tbp[c], acc);
                                zi -= acc;
                            }
                            const float* base = Mm + (size_t)(k0 + lane) * MST + k0;
                            #pragma unroll
                            for (int j = 0; j < 16; ++j)
                                rowk[j] = (j < lane) ? base[j] : 0.f;
                        } else {
                            #pragma unroll
                            for (int j = 0; j < 16; ++j) rowk[j] = 0.f;
                        }
                        #pragma unroll
                        for (int k = 0; k < 16; ++k) {
                            float tk = __shfl_sync(0xffffffffu, zi * di, k);
                            if (lane > k && lane < 16) zi -= rowk[k] * tk;
                        }
                        if (lane < 16) { msol[k0 + lane] = zi; tbc[lane] = zi * di; }
                    } else if (b > 0) {
                        int i = k0 + 16 + (tid - 32);
                        if (i < NR) {
                            const float* rp = Mm + (size_t)i * MST + (k0 - 16);
                            float acc = 0.f;
                            #pragma unroll
                            for (int c = 0; c < 16; ++c) acc = fmaf(rp[c], tbp[c], acc);
                            msol[i] -= acc;
                        }
                    }
                    __syncthreads();
                    float* t = tbp; tbp = tbc; tbc = t;
                }
                // backward
                #pragma unroll 1
                for (int b = 3; b >= 0; --b) {
                    const int k0 = 16 * b;
                    if (wid == 0) {
                        float zi = 0.f, di = 0.f, colT[16];
                        if (lane < 16) {
                            zi = msol[k0 + lane];
                            di = mdinv[k0 + lane];
                            if (b < 3) {
                                float acc = 0.f;
                                #pragma unroll
                                for (int c = 0; c < 16; ++c)
                                    acc = fmaf(Mm[(size_t)(k0 + 16 + c) * MST + k0 + lane],
                                               tbp[c], acc);
                                zi -= acc;
                            }
                            #pragma unroll
                            for (int j = 0; j < 16; ++j)
                                colT[j] = (j > lane)
                                          ? Mm[(size_t)(k0 + j) * MST + k0 + lane] : 0.f;
                        } else {
                            #pragma unroll
                            for (int j = 0; j < 16; ++j) colT[j] = 0.f;
                        }
                        #pragma unroll
                        for (int i = 15; i >= 0; --i) {
                            float dv = __shfl_sync(0xffffffffu, zi * di, i);
                            if (lane < i) zi -= colT[i] * dv;
                        }
                        if (lane < 16) {
                            float d = zi * di;
                            uv[k0 + lane] = d;
                            tbc[lane] = d;
                        }
                    } else if (b < 3) {
                        int t = tid - 32;
                        if (t < k0) {
                            float acc = 0.f;
                            #pragma unroll
                            for (int c = 0; c < 16; ++c)
                                acc = fmaf(Mm[(size_t)(k0 + 16 + c) * MST + t], tbp[c], acc);
                            msol[t] -= acc;
                        }
                    }
                    __syncthreads();
                    float* t = tbp; tbp = tbc; tbc = t;
                }
            }

            // ---- dy = w - E^{-1} U u ; damped update ----
            if (tid < NAS) {
                float lu = urow_dot(tid, uv);
                dyv[tid] = wv[tid] - ev[tid] * lu;
            }
            float ddy = (tid < NAS) ? dyv[tid] : 0.f;
            float yy  = (tid < NAS) ? yv[tid]  : 1.f;
            float ratio = (ddy < 0.f) ? (-yy / ddy) : 1e30f;
            if (tid >= NAS) ratio = 1e30f;
            float tstep = fminf(1.0f, 0.9f * blk_min(ratio, red, tid));
            if (tid < NAS) yv[tid] = fmaxf(yy + tstep * ddy, 1e-12f);
            __syncthreads();

            if (last) break;
        }

        // ---- z = y / sum(y) ----
        float yy = (tid < NAS) ? yv[tid] : 0.f;
        float ssum = blk_sum(yy, red, tid);
        if (tid < NAS) out_z[(size_t)s * NAS + tid] = yy / ssum;
        __syncthreads();
    }
}

// ---------------------------------------------------------------------------
extern "C" void kernel_launch(void* const* d_in, const int* in_sizes, int n_in,
                              void* d_out, int out_size)
{
    const float* x     = (const float*)d_in[0];
    const float* Sigma = (const float*)d_in[1];
    const float* W1    = (const float*)d_in[2];
    const float* b1    = (const float*)d_in[3];
    const float* W2    = (const float*)d_in[4];
    const float* b2    = (const float*)d_in[5];
    float* out = (float*)d_out;

    cudaFuncSetAttribute(newton_kernel,
                         cudaFuncAttributeMaxDynamicSharedMemorySize, SMEM_BYTES);

    mlp_kernel<<<BATCH, 256>>>(x, W1, b1, W2, b2, out);
    newton_kernel<<<GRID2, 512, SMEM_BYTES>>>(Sigma, out);
}

// round 16
// speedup vs baseline: 1.0451x; 1.0451x over previous
#include <cuda_runtime.h>

// ---------------------------------------------------------------------------
// ModelBasedNet: MLP -> softmax risk budgets -> per-sample risk-budget QP via
// damped Newton, Woodbury on the exact rank-64 structure of Sigma.
// Round 16: round-9 base (best passing: 641.7us) + ILP fix: multi-accumulator
// FMA chains in urow_dot (4 acc), utv (2 acc), and the pivoted-setup column
// dot (float4 partials). Math identical up to re-association.
// Outputs: z (512x200) then b (512x200) into d_out.
// ---------------------------------------------------------------------------

constexpr int BATCH = 512;
constexpr int NFE   = 128;
constexpr int NAS   = 200;
constexpr int HID   = 256;
constexpr int NR    = 64;    // rank of Sigma - 0.1I
constexpr int NIT   = 20;
constexpr int LST   = 68;    // U row stride (17 quads -> conflict-free)
constexpr int MST   = 65;    // Mm row stride
constexpr int NTILE = 136;   // lower-triangle 4x4 tiles of 64x64
constexpr int GRID2 = 304;
constexpr float ALPHA_LR = 0.01f;
constexpr float BMIN     = 1e-4f;
constexpr float SIG_DIAG = 0.1f;
constexpr float KKT_TOL  = 1e-3f;

// smem layout (floats)
constexpr int OFF_LM  = 0;                    // 200*68 = 13600 (U)
constexpr int OFF_MM  = OFF_LM + NAS * LST;   // 64*65  = 4160
constexpr int OFF_GP  = OFF_MM + NR * MST;    // 2*136*16 = 4352
constexpr int OFF_YV  = OFF_GP + 2 * NTILE * 16;
constexpr int OFF_BV  = OFF_YV + NAS;
constexpr int OFF_WV  = OFF_BV + NAS;
constexpr int OFF_EV  = OFF_WV + NAS;
constexpr int OFF_DY  = OFF_EV + NAS;
constexpr int OFF_DG  = OFF_DY + NAS;         // pivot diag (200)
constexpr int OFF_TY  = OFF_DG + NAS;         // 64
constexpr int OFF_MS  = OFF_TY + NR;          // 64
constexpr int OFF_UV  = OFF_MS + NR;          // 64
constexpr int OFF_MD  = OFF_UV + NR;          // 64
constexpr int OFF_RED = OFF_MD + NR;          // 512
constexpr int OFF_TB  = OFF_RED + 512;        // 16
constexpr int OFF_LB  = OFF_TB + 16;          // 32
constexpr int OFF_RI  = OFF_LB + 32;          // 32 (int)
constexpr int SMEM_FLOATS = OFF_RI + 32;
constexpr int SMEM_BYTES  = SMEM_FLOATS * 4;

__device__ float g_bc[BATCH * NAS];
__device__ unsigned int g_work;

// ---- block reductions (512 threads, 3 barriers) ----------------------------
__device__ __forceinline__ float blk_sum(float v, float* red, int tid) {
    __syncthreads();
    #pragma unroll
    for (int o = 16; o > 0; o >>= 1) v += __shfl_xor_sync(0xffffffffu, v, o);
    if ((tid & 31) == 0) red[tid >> 5] = v;
    __syncthreads();
    if (tid < 16) {
        float x = red[tid];
        #pragma unroll
        for (int o = 8; o > 0; o >>= 1) x += __shfl_xor_sync(0xffffu, x, o);
        if (tid == 0) red[0] = x;
    }
    __syncthreads();
    return red[0];
}
__device__ __forceinline__ float blk_max(float v, float* red, int tid) {
    __syncthreads();
    #pragma unroll
    for (int o = 16; o > 0; o >>= 1) v = fmaxf(v, __shfl_xor_sync(0xffffffffu, v, o));
    if ((tid & 31) == 0) red[tid >> 5] = v;
    __syncthreads();
    if (tid < 16) {
        float x = red[tid];
        #pragma unroll
        for (int o = 8; o > 0; o >>= 1) x = fmaxf(x, __shfl_xor_sync(0xffffu, x, o));
        if (tid == 0) red[0] = x;
    }
    __syncthreads();
    return red[0];
}
__device__ __forceinline__ float blk_min(float v, float* red, int tid) {
    __syncthreads();
    #pragma unroll
    for (int o = 16; o > 0; o >>= 1) v = fminf(v, __shfl_xor_sync(0xffffffffu, v, o));
    if ((tid & 31) == 0) red[tid >> 5] = v;
    __syncthreads();
    if (tid < 16) {
        float x = red[tid];
        #pragma unroll
        for (int o = 8; o > 0; o >>= 1) x = fminf(x, __shfl_xor_sync(0xffffu, x, o));
        if (tid == 0) red[0] = x;
    }
    __syncthreads();
    return red[0];
}

// ---- shuffle-register 8x8 diagonal block factorization (one warp) ----------
__device__ __forceinline__ void diag_factor_rs(
    float* M, int st, float* dinv8, float* Lblk, int k0, int lane)
{
    float row[8];
    float dinv_own = 0.f;
    float* base = M + (size_t)(k0 + lane) * st + k0;   // valid only lane<8
    if (lane < 8) {
        #pragma unroll
        for (int j = 0; j < 8; ++j) row[j] = (j <= lane) ? base[j] : 0.f;
    } else {
        #pragma unroll
        for (int j = 0; j < 8; ++j) row[j] = 0.f;
    }
    #pragma unroll
    for (int k = 0; k < 8; ++k) {
        float dk   = __shfl_sync(0xffffffffu, row[k], k);
        float dinv = 1.0f / dk;
        if (lane == k) dinv_own = dinv;
        float f = row[k] * dinv;
        #pragma unroll
        for (int j = k + 1; j < 8; ++j) {
            float c = __shfl_sync(0xffffffffu, row[k], j);
            if (lane >= j) row[j] -= f * c;
        }
    }
    if (lane < 8) {
        #pragma unroll
        for (int j = 0; j < 8; ++j)
            if (j <= lane) base[j] = row[j];
        dinv8[lane] = dinv_own;
    }
    #pragma unroll
    for (int c = 0; c < 8; ++c) {
        float ic = __shfl_sync(0xffffffffu, dinv_own, c);
        if (lane < 8 && c < lane)
            Lblk[(lane * (lane - 1)) / 2 + c] = row[c] * ic;
    }
}

__device__ __forceinline__ void block_apply8(float* a, const float* Lblk) {
    a[1] -= a[0] * Lblk[0];
    a[2] -= a[0] * Lblk[1] + a[1] * Lblk[2];
    a[3] -= a[0] * Lblk[3] + a[1] * Lblk[4] + a[2] * Lblk[5];
    a[4] -= a[0] * Lblk[6] + a[1] * Lblk[7] + a[2] * Lblk[8] + a[3] * Lblk[9];
    a[5] -= a[0] * Lblk[10] + a[1] * Lblk[11] + a[2] * Lblk[12] + a[3] * Lblk[13]
          + a[4] * Lblk[14];
    a[6] -= a[0] * Lblk[15] + a[1] * Lblk[16] + a[2] * Lblk[17] + a[3] * Lblk[18]
          + a[4] * Lblk[19] + a[5] * Lblk[20];
    a[7] -= a[0] * Lblk[21] + a[1] * Lblk[22] + a[2] * Lblk[23] + a[3] * Lblk[24]
          + a[4] * Lblk[25] + a[5] * Lblk[26] + a[6] * Lblk[27];
}

// ---------------------------------------------------------------------------
__global__ __launch_bounds__(256) void mlp_kernel(
    const float* __restrict__ x,
    const float* __restrict__ W1, const float* __restrict__ b1,
    const float* __restrict__ W2, const float* __restrict__ b2,
    float* __restrict__ out)
{
    __shared__ float xs[NFE];
    __shared__ float hs[HID];
    __shared__ float ls[NAS];
    __shared__ float red[256];

    if (blockIdx.x == 0 && threadIdx.x == 0) g_work = 0;

    const int s    = blockIdx.x;
    const int tid  = threadIdx.x;
    const int warp = tid >> 5;
    const int lane = tid & 31;

    if (tid < NFE) xs[tid] = x[s * NFE + tid];
    __syncthreads();

    for (int r = 0; r < 32; ++r) {
        int j = warp * 32 + r;
        const float4* w = (const float4*)(W1 + (size_t)j * NFE);
        float4 a = w[lane];
        int k = lane * 4;
        float acc = a.x * xs[k] + a.y * xs[k + 1] + a.z * xs[k + 2] + a.w * xs[k + 3];
        #pragma unroll
        for (int o = 16; o > 0; o >>= 1) acc += __shfl_down_sync(0xffffffffu, acc, o);
        if (lane == 0) {
            float v = acc + b1[j];
            hs[j] = (v >= 0.f) ? v : ALPHA_LR * v;
        }
    }
    __syncthreads();

    for (int r = 0; r < 25; ++r) {
        int j = warp * 25 + r;
        const float4* w = (const float4*)(W2 + (size_t)j * HID);
        float acc = 0.f;
        #pragma unroll
        for (int c = 0; c < 2; ++c) {
            float4 a = w[lane * 2 + c];
            int k = (lane * 2 + c) * 4;
            acc += a.x * hs[k] + a.y * hs[k + 1] + a.z * hs[k + 2] + a.w * hs[k + 3];
        }
        #pragma unroll
        for (int o = 16; o > 0; o >>= 1) acc += __shfl_down_sync(0xffffffffu, acc, o);
        if (lane == 0) ls[j] = acc + b2[j];
    }
    __syncthreads();

    red[tid] = (tid < NAS) ? ls[tid] : -3.0e38f;
    __syncthreads();
    for (int o = 128; o > 0; o >>= 1) {
        if (tid < o) red[tid] = fmaxf(red[tid], red[tid + o]);
        __syncthreads();
    }
    float m = red[0];
    __syncthreads();

    float e = (tid < NAS) ? expf(ls[tid] - m) : 0.f;
    red[tid] = e;
    __syncthreads();
    for (int o = 128; o > 0; o >>= 1) {
        if (tid < o) red[tid] += red[tid + o];
        __syncthreads();
    }
    float denom = red[0];
    __syncthreads();

    float bb = e / denom;
    if (tid < NAS) out[(size_t)BATCH * NAS + (size_t)s * NAS + tid] = bb;

    float bcv = fmaxf(bb, BMIN);
    red[tid] = (tid < NAS) ? bcv : 0.f;
    __syncthreads();
    for (int o = 128; o > 0; o >>= 1) {
        if (tid < o) red[tid] += red[tid + o];
        __syncthreads();
    }
    float s2 = red[0];
    __syncthreads();
    if (tid < NAS) g_bc[s * NAS + tid] = bcv / s2;
}

// ---------------------------------------------------------------------------
__global__ __launch_bounds__(512, 2) void newton_kernel(
    const float* __restrict__ Sigma, float* __restrict__ out_z)
{
    extern __shared__ float sm[];
    float* Um    = sm + OFF_LM;
    float* Mm    = sm + OFF_MM;
    float* Gp    = sm + OFF_GP;
    float* yv    = sm + OFF_YV;
    float* bv    = sm + OFF_BV;
    float* wv    = sm + OFF_WV;
    float* ev    = sm + OFF_EV;
    float* dyv   = sm + OFF_DY;
    float* diag  = sm + OFF_DG;
    float* tyv   = sm + OFF_TY;
    float* msol  = sm + OFF_MS;
    float* uv    = sm + OFF_UV;
    float* mdinv = sm + OFF_MD;
    float* red   = sm + OFF_RED;
    float* tb    = sm + OFF_TB;
    float* Lblk  = sm + OFF_LB;
    int*   redi  = (int*)(sm + OFF_RI);

    __shared__ int s_sample;

    const int tid  = threadIdx.x;
    const int wid  = tid >> 5;
    const int lane = tid & 31;

    // gram tile assignment (fixed per thread)
    const bool gact = (tid < 3 * NTILE);
    int tPt = 0, tQt = 0, tIdx = 0, tI0 = 0, tIe = 0;
    if (gact) {
        tIdx = tid % NTILE;
        int h = tid / NTILE;
        int p = (int)((sqrtf(8.f * (float)tIdx + 1.f) - 1.f) * 0.5f);
        while (p * (p + 1) / 2 > tIdx) --p;
        while ((p + 1) * (p + 2) / 2 <= tIdx) ++p;
        tPt = p;
        tQt = tIdx - p * (p + 1) / 2;
        tI0 = h * 67;
        tIe = (h == 2) ? NAS : tI0 + 67;
    }

    // U^T * vec -> outv[64]  (2 independent accumulators per thread)
    auto utv = [&](const float* v, float* outv) {
        int c = tid & 63, h = tid >> 6;
        int i0 = h * 25;
        float a0 = 0.f, a1 = 0.f;
        #pragma unroll 4
        for (int i = i0; i + 1 < i0 + 25; i += 2) {
            a0 = fmaf(Um[i * LST + c], v[i], a0);
            a1 = fmaf(Um[(i + 1) * LST + c], v[i + 1], a1);
        }
        a0 = fmaf(Um[(i0 + 24) * LST + c], v[i0 + 24], a0);
        red[tid] = a0 + a1;
        __syncthreads();
        if (tid < NR) {
            float t2 = 0.f;
            #pragma unroll
            for (int h2 = 0; h2 < 8; ++h2) t2 += red[tid + 64 * h2];
            outv[tid] = t2;
        }
        __syncthreads();
    };

    // (U * t64)_i for row i  (4 independent accumulators)
    auto urow_dot = [&](int i, const float* t64) -> float {
        const float4* lr  = (const float4*)(Um + i * LST);
        const float4* tv4 = (const float4*)t64;
        float a0 = 0.f, a1 = 0.f, a2 = 0.f, a3 = 0.f;
        #pragma unroll
        for (int c = 0; c < 16; ++c) {
            float4 a = lr[c], b4 = tv4[c];
            a0 = fmaf(a.x, b4.x, a0); a1 = fmaf(a.y, b4.y, a1);
            a2 = fmaf(a.z, b4.z, a2); a3 = fmaf(a.w, b4.w, a3);
        }
        return (a0 + a1) + (a2 + a3);
    };

    for (;;) {
        if (tid == 0) s_sample = (int)atomicAdd(&g_work, 1u);
        __syncthreads();
        const int s = s_sample;
        if (s >= BATCH) break;

        const float* S = Sigma + (size_t)s * NAS * NAS;
        if (tid < NAS) {
            bv[tid]   = g_bc[s * NAS + tid];
            diag[tid] = S[(size_t)tid * NAS + tid] - SIG_DIAG;
        }
        __syncthreads();

        // ======== setup: diagonally-pivoted Cholesky, 64 columns ===========
        for (int k = 0; k < NR; ++k) {
            // warp 0: argmax of residual diagonal
            if (tid < 32) {
                float v = -1e30f; int ix = 0;
                for (int i = lane; i < NAS; i += 32) {
                    float d = diag[i];
                    if (d > v) { v = d; ix = i; }
                }
                #pragma unroll
                for (int o = 16; o > 0; o >>= 1) {
                    float ov = __shfl_xor_sync(0xffffffffu, v, o);
                    int   oi = __shfl_xor_sync(0xffffffffu, ix, o);
                    if (ov > v) { v = ov; ix = oi; }
                }
                if (lane == 0) { red[0] = v; redi[0] = ix; }
            }
            __syncthreads();
            const int   p  = redi[0];
            const float rs = rsqrtf(fmaxf(red[0], 1e-20f));

            // column k: U[:,k] = (Sigma[:,p] - U U[p,:k]^T) * rs
            // float4 partial sums -> 4 independent FMA chains
            if (tid < NAS) {
                float acc = S[(size_t)p * NAS + tid];
                if (tid == p) acc -= SIG_DIAG;
                const float4* Ui4 = (const float4*)(Um + tid * LST);
                const float4* Up4 = (const float4*)(Um + p * LST);
                int k4 = k >> 2;
                float p0 = 0.f, p1 = 0.f, p2 = 0.f, p3 = 0.f;
                for (int c = 0; c < k4; ++c) {
                    float4 a = Ui4[c], b4 = Up4[c];
                    p0 = fmaf(a.x, b4.x, p0); p1 = fmaf(a.y, b4.y, p1);
                    p2 = fmaf(a.z, b4.z, p2); p3 = fmaf(a.w, b4.w, p3);
                }
                acc -= (p0 + p1) + (p2 + p3);
                for (int c = k4 * 4; c < k; ++c)
                    acc -= Um[tid * LST + c] * Um[p * LST + c];
                float val = acc * rs;
                Um[tid * LST + k] = val;
                if (tid == p) diag[tid] = -1e30f;
                else          diag[tid] -= val * val;
            }
            __syncthreads();
        }

        // ======== y0 = b / sqrt(b'Sb),  b'Sb = |U^T b|^2 + 0.1|b|^2 ========
        utv(bv, tyv);
        {
            float q = 0.f;
            if (tid < NR)  q += tyv[tid] * tyv[tid];
            if (tid < NAS) q += SIG_DIAG * bv[tid] * bv[tid];
            float Q = blk_sum(q, red, tid);
            if (tid < NAS) yv[tid] = bv[tid] * rsqrtf(Q);
            __syncthreads();
        }

        // ======== Newton iterations =========================================
        for (int it = 0; it < NIT; ++it) {
            // Sy = U(U^T y) + 0.1 y ; g = b/y - Sy ; E = 0.1 + b/y^2
            utv(yv, tyv);
            float kkt = 0.f;
            if (tid < NAS) {
                float sy = urow_dot(tid, tyv) + SIG_DIAG * yv[tid];
                float yy = yv[tid];
                float g  = bv[tid] / yy - sy;
                float E  = SIG_DIAG + bv[tid] / (yy * yy);
                float ei = 1.0f / E;
                ev[tid] = ei;
                wv[tid] = ei * g;
                kkt = fabsf(g) * yy / bv[tid];
            }
            const bool last = (blk_max(kkt, red, tid) < KKT_TOL);

            // ---- gram: lower triangle of Mm = U^T E^{-1} U (+I) ----
            if (gact) {
                const float* lp = Um + 4 * tPt;
                const float* lq = Um + 4 * tQt;
                float acc[16];
                #pragma unroll
                for (int e = 0; e < 16; ++e) acc[e] = 0.f;
                for (int i = tI0; i < tIe; ++i) {
                    float4 a  = *(const float4*)(lp + i * LST);
                    float4 b4 = *(const float4*)(lq + i * LST);
                    float e = ev[i];
                    float4 be = make_float4(b4.x * e, b4.y * e, b4.z * e, b4.w * e);
                    acc[0]  = fmaf(a.x, be.x, acc[0]);  acc[1]  = fmaf(a.x, be.y, acc[1]);
                    acc[2]  = fmaf(a.x, be.z, acc[2]);  acc[3]  = fmaf(a.x, be.w, acc[3]);
                    acc[4]  = fmaf(a.y, be.x, acc[4]);  acc[5]  = fmaf(a.y, be.y, acc[5]);
                    acc[6]  = fmaf(a.y, be.z, acc[6]);  acc[7]  = fmaf(a.y, be.w, acc[7]);
                    acc[8]  = fmaf(a.z, be.x, acc[8]);  acc[9]  = fmaf(a.z, be.y, acc[9]);
                    acc[10] = fmaf(a.z, be.z, acc[10]); acc[11] = fmaf(a.z, be.w, acc[11]);
                    acc[12] = fmaf(a.w, be.x, acc[12]); acc[13] = fmaf(a.w, be.y, acc[13]);
                    acc[14] = fmaf(a.w, be.z, acc[14]); acc[15] = fmaf(a.w, be.w, acc[15]);
                }
                if (tid < NTILE) {
                    #pragma unroll
                    for (int e = 0; e < 16; ++e)
                        Mm[(4 * tPt + (e >> 2)) * MST + 4 * tQt + (e & 3)] = acc[e];
                } else {
                    float* gp = Gp + (tid / NTILE - 1) * (NTILE * 16) + tIdx * 16;
                    #pragma unroll
                    for (int e = 0; e < 16; ++e) gp[e] = acc[e];
                }
            }
            __syncthreads();
            for (int idx = tid; idx < NR * NR; idx += 512) {
                int row = idx >> 6, col = idx & 63;
                if (col <= row) {
                    int rp = row >> 2;
                    int ti = rp * (rp + 1) / 2 + (col >> 2);
                    int e  = (row & 3) * 4 + (col & 3);
                    float v = Mm[row * MST + col]
                            + Gp[ti * 16 + e] + Gp[NTILE * 16 + ti * 16 + e];
                    if (row == col) v += 1.0f;
                    Mm[row * MST + col] = v;
                }
            }
            __syncthreads();

            // ---- Cholesky of Mm (64, unscaled LDL, panels of 8) ----
            for (int k0 = 0; k0 < NR; k0 += 8) {
                const int k1 = k0 + 8;
                if (tid < 32) diag_factor_rs(Mm, MST, mdinv + k0, Lblk, k0, lane);
                __syncthreads();
                if (k1 >= NR) break;
                const int m = NR - k1;
                if (tid < m) {
                    float* rp = Mm + (size_t)(k1 + tid) * MST + k0;
                    float a[8];
                    #pragma unroll
                    for (int c = 0; c < 8; ++c) a[c] = rp[c];
                    block_apply8(a, Lblk);
                    #pragma unroll
                    for (int c = 0; c < 8; ++c) rp[c] = a[c];
                }
                __syncthreads();
                for (int i = k1 + wid; i < NR; i += 16) {
                    const float* rp = Mm + (size_t)i * MST + k0;
                    float f[8];
                    #pragma unroll
                    for (int c = 0; c < 8; ++c) f[c] = rp[c] * mdinv[k0 + c];
                    int width = i - k1 + 1;
                    for (int jo = lane; jo < width; jo += 32) {
                        const float* aj = Mm + (size_t)(k1 + jo) * MST + k0;
                        float d0 = f[0] * aj[0], e0 = f[1] * aj[1];
                        d0 = fmaf(f[2], aj[2], d0); e0 = fmaf(f[3], aj[3], e0);
                        d0 = fmaf(f[4], aj[4], d0); e0 = fmaf(f[5], aj[5], e0);
                        d0 = fmaf(f[6], aj[6], d0); e0 = fmaf(f[7], aj[7], e0);
                        Mm[(size_t)i * MST + k1 + jo] -= (d0 + e0);
                    }
                }
                __syncthreads();
            }

            // ---- msol = U^T w ; solve M u = msol ----
            utv(wv, msol);

            #pragma unroll 1
            for (int k0 = 0; k0 < NR; k0 += 16) {        // forward
                const int k1 = k0 + 16;
                if (tid < 32) {
                    float zi = 0.f, di = 0.f, rowk[16];
                    const float* base = Mm + (size_t)(k0 + (tid & 15)) * MST + k0;
                    if (tid < 16) { zi = msol[k0 + tid]; di = mdinv[k0 + tid]; }
                    #pragma unroll
                    for (int j = 0; j < 16; ++j)
                        rowk[j] = (tid < 16 && j < tid) ? base[j] : 0.f;
                    #pragma unroll
                    for (int k = 0; k < 16; ++k) {
                        float tk = __shfl_sync(0xffffffffu, zi * di, k);
                        if (tid > k && tid < 16) zi -= rowk[k] * tk;
                    }
                    if (tid < 16) { msol[k0 + tid] = zi; tb[tid] = zi * di; }
                }
                __syncthreads();
                int i = k1 + tid;
                if (i < NR) {
                    const float* rp = Mm + (size_t)i * MST + k0;
                    float acc = 0.f;
                    #pragma unroll
                    for (int c = 0; c < 16; ++c) acc = fmaf(rp[c], tb[c], acc);
                    msol[i] -= acc;
                }
                __syncthreads();
            }
            #pragma unroll 1
            for (int k0 = NR - 16; k0 >= 0; k0 -= 16) {  // backward
                if (tid < 32) {
                    float zi = 0.f, di = 0.f, colT[16];
                    if (tid < 16) { zi = msol[k0 + tid]; di = mdinv[k0 + tid]; }
                    #pragma unroll
                    for (int j = 0; j < 16; ++j)
                        colT[j] = (tid < 16 && j > tid)
                                  ? Mm[(size_t)(k0 + j) * MST + k0 + tid] : 0.f;
                    #pragma unroll
                    for (int i = 15; i >= 0; --i) {
                        float dv = __shfl_sync(0xffffffffu, zi * di, i);
                        if (tid < i) zi -= colT[i] * dv;
                    }
                    if (tid < 16) { float d = zi * di; uv[k0 + tid] = d; tb[tid] = d; }
                }
                __syncthreads();
                if (tid < k0) {
                    float acc = 0.f;
                    #pragma unroll
                    for (int c = 0; c < 16; ++c)
                        acc = fmaf(Mm[(size_t)(k0 + c) * MST + tid], tb[c], acc);
                    msol[tid] -= acc;
                }
                __syncthreads();
            }

            // ---- dy = w - E^{-1} U u ; damped update ----
            if (tid < NAS) {
                float lu = urow_dot(tid, uv);
                dyv[tid] = wv[tid] - ev[tid] * lu;
            }
            float ddy = (tid < NAS) ? dyv[tid] : 0.f;
            float yy  = (tid < NAS) ? yv[tid]  : 1.f;
            float ratio = (ddy < 0.f) ? (-yy / ddy) : 1e30f;
            if (tid >= NAS) ratio = 1e30f;
            float tstep = fminf(1.0f, 0.9f * blk_min(ratio, red, tid));
            if (tid < NAS) yv[tid] = fmaxf(yy + tstep * ddy, 1e-12f);
            __syncthreads();

            if (last) break;
        }

        // ---- z = y / sum(y) ----
        float yy = (tid < NAS) ? yv[tid] : 0.f;
        float ssum = blk_sum(yy, red, tid);
        if (tid < NAS) out_z[(size_t)s * NAS + tid] = yy / ssum;
        __syncthreads();
    }
}

// ---------------------------------------------------------------------------
extern "C" void kernel_launch(void* const* d_in, const int* in_sizes, int n_in,
                              void* d_out, int out_size)
{
    const float* x     = (const float*)d_in[0];
    const float* Sigma = (const float*)d_in[1];
    const float* W1    = (const float*)d_in[2];
    const float* b1    = (const float*)d_in[3];
    const float* W2    = (const float*)d_in[4];
    const float* b2    = (const float*)d_in[5];
    float* out = (float*)d_out;

    cudaFuncSetAttribute(newton_kernel,
                         cudaFuncAttributeMaxDynamicSharedMemorySize, SMEM_BYTES);

    mlp_kernel<<<BATCH, 256>>>(x, W1, b1, W2, b2, out);
    newton_kernel<<<GRID2, 512, SMEM_BYTES>>>(Sigma, out);
}